// round 1
// baseline (speedup 1.0000x reference)
#include <cuda_runtime.h>

#define N_NODES 100000
#define N_EDGES 600000
#define DIM 128
#define KTOT 640   // 512 (4 bases x 128) + 128 (root)

// ---------------- scratch (static device globals; no runtime alloc) ----------------
__device__ float g_h0[(size_t)N_NODES * DIM];          // layer-1 input (gathered embeddings)
__device__ float g_h1[(size_t)N_NODES * DIM];          // layer-1 output / layer-2 input
__device__ float g_S[(size_t)N_NODES * 512];           // aggregated basis-space features
__device__ float4 g_coeff[N_EDGES];                    // per-edge norm*att row
__device__ int   g_deg[N_NODES];
__device__ int   g_rowptr[N_NODES + 1];
__device__ int   g_cursor[N_NODES];
__device__ float g_invdeg[N_NODES];
__device__ int   g_eid[N_EDGES];

// ---------------- CSR build ----------------
__global__ void k_zero_deg() {
    int i = blockIdx.x * blockDim.x + threadIdx.x;
    if (i < N_NODES) g_deg[i] = 0;
}

__global__ void k_hist(const int* __restrict__ dst) {
    int e = blockIdx.x * blockDim.x + threadIdx.x;
    if (e < N_EDGES) atomicAdd(&g_deg[dst[e]], 1);
}

// single-block Hillis-Steele scan over 100001 entries (exclusive), also fills cursor/invdeg
__global__ void k_scan() {
    __shared__ int sh[1024];
    __shared__ int carry;
    int tid = threadIdx.x;
    if (tid == 0) carry = 0;
    __syncthreads();
    for (int base = 0; base < N_NODES; base += 1024) {
        int i = base + tid;
        int v = (i < N_NODES) ? g_deg[i] : 0;
        sh[tid] = v;
        __syncthreads();
        #pragma unroll
        for (int off = 1; off < 1024; off <<= 1) {
            int t = (tid >= off) ? sh[tid - off] : 0;
            __syncthreads();
            sh[tid] += t;
            __syncthreads();
        }
        int excl = sh[tid] - v + carry;
        if (i < N_NODES) {
            g_rowptr[i] = excl;
            g_cursor[i] = excl;
            g_invdeg[i] = 1.0f / fmaxf((float)v, 1.0f);
        }
        __syncthreads();
        if (tid == 0) carry += sh[1023];
        __syncthreads();
    }
    if (threadIdx.x == 0) g_rowptr[N_NODES] = carry;
}

__global__ void k_scatter(const int* __restrict__ dst) {
    int e = blockIdx.x * blockDim.x + threadIdx.x;
    if (e < N_EDGES) {
        int pos = atomicAdd(&g_cursor[dst[e]], 1);
        g_eid[pos] = e;
    }
}

// ---------------- embedding gather ----------------
__global__ void k_gather(const int* __restrict__ entity, const float4* __restrict__ tbl) {
    int t = blockIdx.x * blockDim.x + threadIdx.x;
    if (t >= N_NODES * 32) return;
    int node = t >> 5;
    int lane = t & 31;
    int ent = entity[node];
    ((float4*)g_h0)[(size_t)node * 32 + lane] = tbl[(size_t)ent * 32 + lane];
}

// ---------------- per-edge coefficients: c = norm * att[type] ----------------
__global__ void k_coeff(const int* __restrict__ etype, const float* __restrict__ enorm,
                        const float4* __restrict__ att) {
    int e = blockIdx.x * blockDim.x + threadIdx.x;
    if (e >= N_EDGES) return;
    float4 a = att[etype[e]];
    float n = enorm[e];
    g_coeff[e] = make_float4(a.x * n, a.y * n, a.z * n, a.w * n);
}

// ---------------- aggregation: warp per dst node, S[d] = invdeg * sum_e c_b * x[src] ----------------
__global__ void k_agg(int layer, const int* __restrict__ src) {
    int gw = (blockIdx.x * blockDim.x + threadIdx.x) >> 5;
    int lane = threadIdx.x & 31;
    if (gw >= N_NODES) return;
    const float4* x4 = (const float4*)(layer == 0 ? g_h0 : g_h1);
    int beg = g_rowptr[gw], end = g_rowptr[gw + 1];
    float4 s0 = make_float4(0.f, 0.f, 0.f, 0.f);
    float4 s1 = s0, s2 = s0, s3 = s0;
    for (int p = beg; p < end; ++p) {
        int e = g_eid[p];
        float4 c = g_coeff[e];
        int sn = src[e];
        float4 xv = x4[(size_t)sn * 32 + lane];
        s0.x = fmaf(c.x, xv.x, s0.x); s0.y = fmaf(c.x, xv.y, s0.y);
        s0.z = fmaf(c.x, xv.z, s0.z); s0.w = fmaf(c.x, xv.w, s0.w);
        s1.x = fmaf(c.y, xv.x, s1.x); s1.y = fmaf(c.y, xv.y, s1.y);
        s1.z = fmaf(c.y, xv.z, s1.z); s1.w = fmaf(c.y, xv.w, s1.w);
        s2.x = fmaf(c.z, xv.x, s2.x); s2.y = fmaf(c.z, xv.y, s2.y);
        s2.z = fmaf(c.z, xv.z, s2.z); s2.w = fmaf(c.z, xv.w, s2.w);
        s3.x = fmaf(c.w, xv.x, s3.x); s3.y = fmaf(c.w, xv.y, s3.y);
        s3.z = fmaf(c.w, xv.z, s3.z); s3.w = fmaf(c.w, xv.w, s3.w);
    }
    float d = g_invdeg[gw];
    s0.x *= d; s0.y *= d; s0.z *= d; s0.w *= d;
    s1.x *= d; s1.y *= d; s1.z *= d; s1.w *= d;
    s2.x *= d; s2.y *= d; s2.z *= d; s2.w *= d;
    s3.x *= d; s3.y *= d; s3.z *= d; s3.w *= d;
    float4* S4 = (float4*)g_S;
    size_t base = (size_t)gw * 128;
    S4[base + lane]      = s0;   // basis 0 : k = 0*128 + 4*lane+t
    S4[base + 32 + lane] = s1;   // basis 1
    S4[base + 64 + lane] = s2;   // basis 2
    S4[base + 96 + lane] = s3;   // basis 3
}

// ---------------- fused GEMM: out = relu?([S | h] @ [basis; root] + bias) ----------------
__device__ __forceinline__ float2 ull2f2(unsigned long long u) {
    float2 f;
    asm("mov.b64 {%0, %1}, %2;" : "=f"(f.x), "=f"(f.y) : "l"(u));
    return f;
}

__global__ __launch_bounds__(256, 2) void k_gemm(
    int layer,
    const float* __restrict__ basis, const float* __restrict__ root,
    const float* __restrict__ bias, float* __restrict__ out_param, int do_relu)
{
    const float* H = (layer == 0) ? g_h0 : g_h1;
    float* out = (layer == 0) ? g_h1 : out_param;

    __shared__ float As[16][130];    // [k][m], padded row (even) for conflict-free stores + 8B align
    __shared__ float Bs2[16][256];   // [k][2n] duplicated pairs for FFMA2

    int tid = threadIdx.x;
    int bm = blockIdx.x * 128;
    int tm = (tid >> 4) << 3;        // 0..120 step 8 (rows, in pairs)
    int tn = (tid & 15) << 3;        // 0..120 step 8 (cols)

    unsigned long long acc[4][8];
    #pragma unroll
    for (int ip = 0; ip < 4; ip++)
        #pragma unroll
        for (int j = 0; j < 8; j++) acc[ip][j] = 0ull;

    for (int kt = 0; kt < KTOT; kt += 16) {
        const float* A; int lda; int kk; const float* W;
        if (kt < 512) { A = g_S; lda = 512; kk = kt;      W = basis + (size_t)kt * 128; }
        else          { A = H;   lda = 128; kk = kt - 512; W = root + (size_t)(kt - 512) * 128; }

        // A tile: 128 rows x 16 cols (one float4 per thread x2)
        #pragma unroll
        for (int it = 0; it < 2; it++) {
            int idx = tid + it * 256;
            int r = idx >> 2;
            int c4 = (idx & 3) << 2;
            int gm = bm + r;
            float4 v = (gm < N_NODES) ? *(const float4*)(A + (size_t)gm * lda + kk + c4)
                                      : make_float4(0.f, 0.f, 0.f, 0.f);
            As[c4 + 0][r] = v.x; As[c4 + 1][r] = v.y;
            As[c4 + 2][r] = v.z; As[c4 + 3][r] = v.w;
        }
        // B tile: 16 rows x 128 cols, written as duplicated pairs (b,b)
        #pragma unroll
        for (int it = 0; it < 2; it++) {
            int idx = tid + it * 256;
            int r = idx >> 5;
            int c = (idx & 31) << 2;
            float4 v = *(const float4*)(W + r * 128 + c);
            *(float4*)&Bs2[r][2 * c]     = make_float4(v.x, v.x, v.y, v.y);
            *(float4*)&Bs2[r][2 * c + 4] = make_float4(v.z, v.z, v.w, v.w);
        }
        __syncthreads();

        #pragma unroll
        for (int k = 0; k < 16; k++) {
            unsigned long long a2[4], b2[8];
            #pragma unroll
            for (int ip = 0; ip < 4; ip++)
                a2[ip] = *(const unsigned long long*)&As[k][tm + 2 * ip];
            #pragma unroll
            for (int j = 0; j < 8; j++)
                b2[j] = *(const unsigned long long*)&Bs2[k][2 * tn + 2 * j];
            #pragma unroll
            for (int ip = 0; ip < 4; ip++)
                #pragma unroll
                for (int j = 0; j < 8; j++)
                    asm("fma.rn.f32x2 %0, %1, %2, %0;"
                        : "+l"(acc[ip][j]) : "l"(a2[ip]), "l"(b2[j]));
        }
        __syncthreads();
    }

    // epilogue: + bias, optional relu, float4 stores
    #pragma unroll
    for (int ip = 0; ip < 4; ip++) {
        int gm0 = bm + tm + 2 * ip;
        float lo[8], hi[8];
        #pragma unroll
        for (int j = 0; j < 8; j++) {
            float2 f = ull2f2(acc[ip][j]);
            float b = bias[tn + j];
            lo[j] = f.x + b;
            hi[j] = f.y + b;
            if (do_relu) { lo[j] = fmaxf(lo[j], 0.f); hi[j] = fmaxf(hi[j], 0.f); }
        }
        if (gm0 < N_NODES) {
            *(float4*)(out + (size_t)gm0 * 128 + tn)     = make_float4(lo[0], lo[1], lo[2], lo[3]);
            *(float4*)(out + (size_t)gm0 * 128 + tn + 4) = make_float4(lo[4], lo[5], lo[6], lo[7]);
        }
        if (gm0 + 1 < N_NODES) {
            *(float4*)(out + (size_t)(gm0 + 1) * 128 + tn)     = make_float4(hi[0], hi[1], hi[2], hi[3]);
            *(float4*)(out + (size_t)(gm0 + 1) * 128 + tn + 4) = make_float4(hi[4], hi[5], hi[6], hi[7]);
        }
    }
}

// ---------------- relation_emb passthrough ----------------
__global__ void k_copyrel(const float* __restrict__ rel, float* __restrict__ out) {
    int i = blockIdx.x * blockDim.x + threadIdx.x;
    if (i < 500 * 128) out[i] = rel[i];
}

// ---------------- launch ----------------
extern "C" void kernel_launch(void* const* d_in, const int* in_sizes, int n_in,
                              void* d_out, int out_size) {
    const int*   entity       = (const int*)d_in[0];
    const int*   edge_index   = (const int*)d_in[1];
    const int*   edge_type    = (const int*)d_in[2];
    const float* edge_norm    = (const float*)d_in[3];
    // d_in[4] = DAD_rel (unused by reference output)
    const float* entity_table = (const float*)d_in[5];
    const float* relation_emb = (const float*)d_in[6];
    const float* basis1 = (const float*)d_in[7];
    const float* att1   = (const float*)d_in[8];
    const float* root1  = (const float*)d_in[9];
    const float* bias1  = (const float*)d_in[10];
    const float* basis2 = (const float*)d_in[11];
    const float* att2   = (const float*)d_in[12];
    const float* root2  = (const float*)d_in[13];
    const float* bias2  = (const float*)d_in[14];

    const int* src = edge_index;
    const int* dst = edge_index + N_EDGES;
    float* out = (float*)d_out;

    // CSR by dst (per-call, deterministic work)
    k_zero_deg<<<(N_NODES + 255) / 256, 256>>>();
    k_hist<<<(N_EDGES + 255) / 256, 256>>>(dst);
    k_scan<<<1, 1024>>>();
    k_scatter<<<(N_EDGES + 255) / 256, 256>>>(dst);

    // h0 = entity_table[entity]
    k_gather<<<(N_NODES * 32 + 255) / 256, 256>>>(entity, (const float4*)entity_table);

    int gemm_blocks = (N_NODES + 127) / 128;

    // layer 1 (relu)
    k_coeff<<<(N_EDGES + 255) / 256, 256>>>(edge_type, edge_norm, (const float4*)att1);
    k_agg<<<(N_NODES * 32 + 255) / 256, 256>>>(0, src);
    k_gemm<<<gemm_blocks, 256>>>(0, basis1, root1, bias1, nullptr, 1);

    // layer 2 (no relu) -> d_out
    k_coeff<<<(N_EDGES + 255) / 256, 256>>>(edge_type, edge_norm, (const float4*)att2);
    k_agg<<<(N_NODES * 32 + 255) / 256, 256>>>(1, src);
    k_gemm<<<gemm_blocks, 256>>>(1, basis2, root2, bias2, out, 0);

    // append relation_emb
    k_copyrel<<<(500 * 128 + 255) / 256, 256>>>(relation_emb, out + (size_t)N_NODES * DIM);
}

// round 3
// speedup vs baseline: 3.7612x; 3.7612x over previous
#include <cuda_runtime.h>
#include <cuda_bf16.h>
#include <cstdint>

#define N_NODES 100000
#define N_EDGES 600000
#define DIM 128
#define KTOT 640   // 512 (4 bases x 128) + 128 (root)

// ---------------- scratch (static device globals; no runtime alloc) ----------------
__device__ float g_h0[(size_t)N_NODES * DIM];
__device__ float g_h1[(size_t)N_NODES * DIM];
__device__ float g_S[(size_t)N_NODES * 512];
__device__ float4 g_coeff[N_EDGES];
__device__ int   g_deg[N_NODES];
__device__ int   g_rowptr[N_NODES + 1];
__device__ int   g_cursor[N_NODES];
__device__ float g_invdeg[N_NODES];
__device__ int   g_eid[N_EDGES];
__device__ __nv_bfloat16 g_Whi[128 * KTOT];   // [n][k]
__device__ __nv_bfloat16 g_Wlo[128 * KTOT];   // [n][k]

// ---------------- helpers ----------------
__device__ __forceinline__ uint32_t smem_u32(const void* p) {
    uint32_t a;
    asm("{ .reg .u64 t; cvta.to.shared.u64 t, %1; cvt.u32.u64 %0, t; }" : "=r"(a) : "l"(p));
    return a;
}
__device__ __forceinline__ void ldm_x4(uint32_t* r, uint32_t addr) {
    asm volatile("ldmatrix.sync.aligned.m8n8.x4.shared.b16 {%0,%1,%2,%3}, [%4];"
                 : "=r"(r[0]), "=r"(r[1]), "=r"(r[2]), "=r"(r[3]) : "r"(addr));
}
__device__ __forceinline__ void mma16816(float* c, const uint32_t* a, const uint32_t* b) {
    asm volatile("mma.sync.aligned.m16n8k16.row.col.f32.bf16.bf16.f32 "
                 "{%0,%1,%2,%3}, {%4,%5,%6,%7}, {%8,%9}, {%0,%1,%2,%3};"
                 : "+f"(c[0]), "+f"(c[1]), "+f"(c[2]), "+f"(c[3])
                 : "r"(a[0]), "r"(a[1]), "r"(a[2]), "r"(a[3]), "r"(b[0]), "r"(b[1]));
}

// ---------------- CSR build ----------------
__global__ void k_zero_deg() {
    int i = blockIdx.x * blockDim.x + threadIdx.x;
    if (i < N_NODES) g_deg[i] = 0;
}
__global__ void k_hist(const int* __restrict__ dst) {
    int e = blockIdx.x * blockDim.x + threadIdx.x;
    if (e < N_EDGES) atomicAdd(&g_deg[dst[e]], 1);
}
__global__ void k_scan() {
    __shared__ int sh[1024];
    __shared__ int carry;
    int tid = threadIdx.x;
    if (tid == 0) carry = 0;
    __syncthreads();
    for (int base = 0; base < N_NODES; base += 1024) {
        int i = base + tid;
        int v = (i < N_NODES) ? g_deg[i] : 0;
        sh[tid] = v;
        __syncthreads();
        #pragma unroll
        for (int off = 1; off < 1024; off <<= 1) {
            int t = (tid >= off) ? sh[tid - off] : 0;
            __syncthreads();
            sh[tid] += t;
            __syncthreads();
        }
        int excl = sh[tid] - v + carry;
        if (i < N_NODES) {
            g_rowptr[i] = excl;
            g_cursor[i] = excl;
            g_invdeg[i] = 1.0f / fmaxf((float)v, 1.0f);
        }
        __syncthreads();
        if (tid == 0) carry += sh[1023];
        __syncthreads();
    }
    if (threadIdx.x == 0) g_rowptr[N_NODES] = carry;
}
__global__ void k_scatter(const int* __restrict__ dst) {
    int e = blockIdx.x * blockDim.x + threadIdx.x;
    if (e < N_EDGES) {
        int pos = atomicAdd(&g_cursor[dst[e]], 1);
        g_eid[pos] = e;
    }
}

// ---------------- embedding gather ----------------
__global__ void k_gather(const int* __restrict__ entity, const float4* __restrict__ tbl) {
    int t = blockIdx.x * blockDim.x + threadIdx.x;
    if (t >= N_NODES * 32) return;
    int node = t >> 5;
    int lane = t & 31;
    int ent = entity[node];
    ((float4*)g_h0)[(size_t)node * 32 + lane] = tbl[(size_t)ent * 32 + lane];
}

// ---------------- per-edge coefficients ----------------
__global__ void k_coeff(const int* __restrict__ etype, const float* __restrict__ enorm,
                        const float4* __restrict__ att) {
    int e = blockIdx.x * blockDim.x + threadIdx.x;
    if (e >= N_EDGES) return;
    float4 a = att[etype[e]];
    float n = enorm[e];
    g_coeff[e] = make_float4(a.x * n, a.y * n, a.z * n, a.w * n);
}

// ---------------- aggregation (warp per dst node) ----------------
__global__ void k_agg(int layer, const int* __restrict__ src) {
    int gw = (blockIdx.x * blockDim.x + threadIdx.x) >> 5;
    int lane = threadIdx.x & 31;
    if (gw >= N_NODES) return;
    const float4* x4 = (const float4*)(layer == 0 ? g_h0 : g_h1);
    int beg = g_rowptr[gw], end = g_rowptr[gw + 1];
    float4 s0 = make_float4(0.f, 0.f, 0.f, 0.f);
    float4 s1 = s0, s2 = s0, s3 = s0;
    for (int p = beg; p < end; ++p) {
        int e = g_eid[p];
        float4 c = g_coeff[e];
        int sn = src[e];
        float4 xv = x4[(size_t)sn * 32 + lane];
        s0.x = fmaf(c.x, xv.x, s0.x); s0.y = fmaf(c.x, xv.y, s0.y);
        s0.z = fmaf(c.x, xv.z, s0.z); s0.w = fmaf(c.x, xv.w, s0.w);
        s1.x = fmaf(c.y, xv.x, s1.x); s1.y = fmaf(c.y, xv.y, s1.y);
        s1.z = fmaf(c.y, xv.z, s1.z); s1.w = fmaf(c.y, xv.w, s1.w);
        s2.x = fmaf(c.z, xv.x, s2.x); s2.y = fmaf(c.z, xv.y, s2.y);
        s2.z = fmaf(c.z, xv.z, s2.z); s2.w = fmaf(c.z, xv.w, s2.w);
        s3.x = fmaf(c.w, xv.x, s3.x); s3.y = fmaf(c.w, xv.y, s3.y);
        s3.z = fmaf(c.w, xv.z, s3.z); s3.w = fmaf(c.w, xv.w, s3.w);
    }
    float d = g_invdeg[gw];
    s0.x *= d; s0.y *= d; s0.z *= d; s0.w *= d;
    s1.x *= d; s1.y *= d; s1.z *= d; s1.w *= d;
    s2.x *= d; s2.y *= d; s2.z *= d; s2.w *= d;
    s3.x *= d; s3.y *= d; s3.z *= d; s3.w *= d;
    float4* S4 = (float4*)g_S;
    size_t base = (size_t)gw * 128;
    S4[base + lane]      = s0;
    S4[base + 32 + lane] = s1;
    S4[base + 64 + lane] = s2;
    S4[base + 96 + lane] = s3;
}

// ---------------- weight split: W[k][n] -> Whi/Wlo [n][k] bf16 ----------------
__global__ void k_prepw(const float* __restrict__ basis, const float* __restrict__ root) {
    int idx = blockIdx.x * blockDim.x + threadIdx.x;
    if (idx >= 128 * KTOT) return;
    int n = idx / KTOT;
    int k = idx % KTOT;
    float w = (k < 512) ? basis[(size_t)k * 128 + n] : root[(size_t)(k - 512) * 128 + n];
    __nv_bfloat16 hi = __float2bfloat16(w);
    __nv_bfloat16 lo = __float2bfloat16(w - __bfloat162float(hi));
    g_Whi[n * KTOT + k] = hi;
    g_Wlo[n * KTOT + k] = lo;
}

// ---------------- HMMA GEMM: out = relu?([S | H] @ W + bias) ----------------
// Tiles: 128(M) x 128(N) x 32(K-chunk). 8 warps: 2(M) x 4(N), warp tile 64x32.
// smem rows padded to 80B (40 bf16) -> conflict-free ldmatrix for any fixed 16B col.
#define ROWS 40   // elements per smem row (32 used + 8 pad)

__global__ __launch_bounds__(256) void k_gemm_mma(
    int layer, const float* __restrict__ bias, float* __restrict__ out_param, int do_relu)
{
    __shared__ __align__(16) __nv_bfloat16 As_hi[128 * ROWS];
    __shared__ __align__(16) __nv_bfloat16 As_lo[128 * ROWS];
    __shared__ __align__(16) __nv_bfloat16 Bs_hi[128 * ROWS];
    __shared__ __align__(16) __nv_bfloat16 Bs_lo[128 * ROWS];

    const float* H = (layer == 0) ? g_h0 : g_h1;
    float* out = (layer == 0) ? g_h1 : out_param;

    int tid = threadIdx.x;
    int wid = tid >> 5;
    int lane = tid & 31;
    int bm = blockIdx.x * 128;
    int wm0 = (wid >> 2) * 64;   // warp M offset within tile
    int wn0 = (wid & 3) * 32;    // warp N offset within tile

    uint32_t a_hi_base = smem_u32(As_hi);
    uint32_t a_lo_base = smem_u32(As_lo);
    uint32_t b_hi_base = smem_u32(Bs_hi);
    uint32_t b_lo_base = smem_u32(Bs_lo);

    float acc[4][4][4];
    #pragma unroll
    for (int i = 0; i < 4; i++)
        #pragma unroll
        for (int j = 0; j < 4; j++)
            #pragma unroll
            for (int q = 0; q < 4; q++) acc[i][j][q] = 0.f;

    // precomputed ldmatrix lane addresses (byte offsets within tile)
    uint32_t a_off = (uint32_t)(lane & 15) * 80 + (uint32_t)(lane >> 4) * 16;
    int bg = lane >> 3;   // 0..3
    uint32_t b_off = (uint32_t)((bg >> 1) * 8 + (lane & 7)) * 80 + (uint32_t)(bg & 1) * 16;

    #pragma unroll 1
    for (int ch = 0; ch < 20; ch++) {
        int kc = ch * 32;
        const float* A;
        int lda, kof;
        if (kc < 512) { A = g_S; lda = 512; kof = kc; }
        else          { A = H;   lda = 128; kof = kc - 512; }

        // ---- A tile: 128 x 32 fp32 -> bf16 hi/lo ----
        #pragma unroll
        for (int i = 0; i < 4; i++) {
            int p = tid + i * 256;       // 0..1023 float4s
            int r = p >> 3;
            int c4 = (p & 7) * 4;
            int gm = bm + r;
            float4 v = (gm < N_NODES) ? *(const float4*)(A + (size_t)gm * lda + kof + c4)
                                      : make_float4(0.f, 0.f, 0.f, 0.f);
            __nv_bfloat16 h[4], l[4];
            h[0] = __float2bfloat16(v.x); l[0] = __float2bfloat16(v.x - __bfloat162float(h[0]));
            h[1] = __float2bfloat16(v.y); l[1] = __float2bfloat16(v.y - __bfloat162float(h[1]));
            h[2] = __float2bfloat16(v.z); l[2] = __float2bfloat16(v.z - __bfloat162float(h[2]));
            h[3] = __float2bfloat16(v.w); l[3] = __float2bfloat16(v.w - __bfloat162float(h[3]));
            uint2 uh, ul;
            uh.x = (uint32_t)__bfloat16_as_ushort(h[0]) | ((uint32_t)__bfloat16_as_ushort(h[1]) << 16);
            uh.y = (uint32_t)__bfloat16_as_ushort(h[2]) | ((uint32_t)__bfloat16_as_ushort(h[3]) << 16);
            ul.x = (uint32_t)__bfloat16_as_ushort(l[0]) | ((uint32_t)__bfloat16_as_ushort(l[1]) << 16);
            ul.y = (uint32_t)__bfloat16_as_ushort(l[2]) | ((uint32_t)__bfloat16_as_ushort(l[3]) << 16);
            *(uint2*)(As_hi + r * ROWS + c4) = uh;
            *(uint2*)(As_lo + r * ROWS + c4) = ul;
        }
        // ---- B tile: 128 n-rows x 32 k bf16 (hi & lo), already split ----
        #pragma unroll
        for (int i = 0; i < 2; i++) {
            int p = tid + i * 256;       // 0..511 uint4s
            int r = p >> 2;
            int c8 = (p & 3) * 8;
            uint4 vh = *(const uint4*)(g_Whi + r * KTOT + kc + c8);
            uint4 vl = *(const uint4*)(g_Wlo + r * KTOT + kc + c8);
            *(uint2*)(Bs_hi + r * ROWS + c8)     = make_uint2(vh.x, vh.y);
            *(uint2*)(Bs_hi + r * ROWS + c8 + 4) = make_uint2(vh.z, vh.w);
            *(uint2*)(Bs_lo + r * ROWS + c8)     = make_uint2(vl.x, vl.y);
            *(uint2*)(Bs_lo + r * ROWS + c8 + 4) = make_uint2(vl.z, vl.w);
        }
        __syncthreads();

        // ---- compute: 2 kk-steps of 16 ----
        #pragma unroll
        for (int kk = 0; kk < 2; kk++) {
            uint32_t kb = (uint32_t)kk * 32;   // byte offset of k-step
            uint32_t ahi[4][4], alo[4][4];
            #pragma unroll
            for (int mf = 0; mf < 4; mf++) {
                uint32_t o = (uint32_t)(wm0 + mf * 16) * 80 + a_off + kb;
                ldm_x4(ahi[mf], a_hi_base + o);
                ldm_x4(alo[mf], a_lo_base + o);
            }
            uint32_t bhi[4][2], blo[4][2];
            #pragma unroll
            for (int pr = 0; pr < 2; pr++) {
                uint32_t o = (uint32_t)(wn0 + pr * 16) * 80 + b_off + kb;
                uint32_t th[4], tl[4];
                ldm_x4(th, b_hi_base + o);
                ldm_x4(tl, b_lo_base + o);
                bhi[pr * 2][0] = th[0]; bhi[pr * 2][1] = th[1];
                bhi[pr * 2 + 1][0] = th[2]; bhi[pr * 2 + 1][1] = th[3];
                blo[pr * 2][0] = tl[0]; blo[pr * 2][1] = tl[1];
                blo[pr * 2 + 1][0] = tl[2]; blo[pr * 2 + 1][1] = tl[3];
            }
            #pragma unroll
            for (int mf = 0; mf < 4; mf++)
                #pragma unroll
                for (int nf = 0; nf < 4; nf++) {
                    mma16816(acc[mf][nf], ahi[mf], bhi[nf]);
                    mma16816(acc[mf][nf], ahi[mf], blo[nf]);
                    mma16816(acc[mf][nf], alo[mf], bhi[nf]);
                }
        }
        __syncthreads();
    }

    // ---- epilogue: bias + optional relu, float2 stores ----
    int qm = lane >> 2;          // 0..7
    int qn = (lane & 3) * 2;     // 0,2,4,6
    #pragma unroll
    for (int nf = 0; nf < 4; nf++) {
        int n = wn0 + nf * 8 + qn;
        float b0 = bias[n], b1 = bias[n + 1];
        #pragma unroll
        for (int mf = 0; mf < 4; mf++) {
            int m0 = bm + wm0 + mf * 16 + qm;
            float2 lo = make_float2(acc[mf][nf][0] + b0, acc[mf][nf][1] + b1);
            float2 hi = make_float2(acc[mf][nf][2] + b0, acc[mf][nf][3] + b1);
            if (do_relu) {
                lo.x = fmaxf(lo.x, 0.f); lo.y = fmaxf(lo.y, 0.f);
                hi.x = fmaxf(hi.x, 0.f); hi.y = fmaxf(hi.y, 0.f);
            }
            if (m0 < N_NODES)     *(float2*)(out + (size_t)m0 * 128 + n) = lo;
            if (m0 + 8 < N_NODES) *(float2*)(out + (size_t)(m0 + 8) * 128 + n) = hi;
        }
    }
}

// ---------------- relation_emb passthrough ----------------
__global__ void k_copyrel(const float* __restrict__ rel, float* __restrict__ out) {
    int i = blockIdx.x * blockDim.x + threadIdx.x;
    if (i < 500 * 128) out[i] = rel[i];
}

// ---------------- launch ----------------
extern "C" void kernel_launch(void* const* d_in, const int* in_sizes, int n_in,
                              void* d_out, int out_size) {
    const int*   entity       = (const int*)d_in[0];
    const int*   edge_index   = (const int*)d_in[1];
    const int*   edge_type    = (const int*)d_in[2];
    const float* edge_norm    = (const float*)d_in[3];
    // d_in[4] = DAD_rel (unused by reference output)
    const float* entity_table = (const float*)d_in[5];
    const float* relation_emb = (const float*)d_in[6];
    const float* basis1 = (const float*)d_in[7];
    const float* att1   = (const float*)d_in[8];
    const float* root1  = (const float*)d_in[9];
    const float* bias1  = (const float*)d_in[10];
    const float* basis2 = (const float*)d_in[11];
    const float* att2   = (const float*)d_in[12];
    const float* root2  = (const float*)d_in[13];
    const float* bias2  = (const float*)d_in[14];

    const int* src = edge_index;
    const int* dst = edge_index + N_EDGES;
    float* out = (float*)d_out;

    // CSR by dst
    k_zero_deg<<<(N_NODES + 255) / 256, 256>>>();
    k_hist<<<(N_EDGES + 255) / 256, 256>>>(dst);
    k_scan<<<1, 1024>>>();
    k_scatter<<<(N_EDGES + 255) / 256, 256>>>(dst);

    // h0 = entity_table[entity]
    k_gather<<<(N_NODES * 32 + 255) / 256, 256>>>(entity, (const float4*)entity_table);

    int gemm_blocks = (N_NODES + 127) / 128;   // 782

    // layer 1 (relu)
    k_coeff<<<(N_EDGES + 255) / 256, 256>>>(edge_type, edge_norm, (const float4*)att1);
    k_agg<<<(N_NODES * 32 + 255) / 256, 256>>>(0, src);
    k_prepw<<<(128 * KTOT + 255) / 256, 256>>>(basis1, root1);
    k_gemm_mma<<<gemm_blocks, 256>>>(0, bias1, nullptr, 1);

    // layer 2 (no relu) -> d_out
    k_coeff<<<(N_EDGES + 255) / 256, 256>>>(edge_type, edge_norm, (const float4*)att2);
    k_agg<<<(N_NODES * 32 + 255) / 256, 256>>>(1, src);
    k_prepw<<<(128 * KTOT + 255) / 256, 256>>>(basis2, root2);
    k_gemm_mma<<<gemm_blocks, 256>>>(1, bias2, out, 0);

    // append relation_emb
    k_copyrel<<<(500 * 128 + 255) / 256, 256>>>(relation_emb, out + (size_t)N_NODES * DIM);
}

// round 4
// speedup vs baseline: 4.5715x; 1.2154x over previous
#include <cuda_runtime.h>
#include <cuda_bf16.h>
#include <cstdint>

#define N_NODES 100000
#define N_EDGES 600000
#define DIM 128
#define KTOT 640   // 512 (4 bases x 128) + 128 (root)

// ---------------- scratch (static device globals; no runtime alloc) ----------------
__device__ float g_h0[(size_t)N_NODES * DIM];
__device__ float g_h1[(size_t)N_NODES * DIM];
__device__ __nv_bfloat16 g_A1hi[(size_t)N_NODES * KTOT];  // layer-1 GEMM A = [S1 | h0]
__device__ __nv_bfloat16 g_A1lo[(size_t)N_NODES * KTOT];
__device__ __nv_bfloat16 g_A2hi[(size_t)N_NODES * KTOT];  // layer-2 GEMM A = [S2 | h1]
__device__ __nv_bfloat16 g_A2lo[(size_t)N_NODES * KTOT];
__device__ float4 g_csr_coeff[N_EDGES];
__device__ int   g_csr_src[N_EDGES];
__device__ int   g_eid[N_EDGES];
__device__ int   g_deg[N_NODES];
__device__ int   g_rowptr[N_NODES + 1];
__device__ int   g_cursor[N_NODES];
__device__ float g_invdeg[N_NODES];
__device__ int   g_bsum[128];
__device__ int   g_boff[129];
__device__ __nv_bfloat16 g_Whi[128 * KTOT];   // [n][k]
__device__ __nv_bfloat16 g_Wlo[128 * KTOT];   // [n][k]

// ---------------- helpers ----------------
__device__ __forceinline__ uint32_t smem_u32(const void* p) {
    uint32_t a;
    asm("{ .reg .u64 t; cvta.to.shared.u64 t, %1; cvt.u32.u64 %0, t; }" : "=r"(a) : "l"(p));
    return a;
}
__device__ __forceinline__ void ldm_x4(uint32_t* r, uint32_t addr) {
    asm volatile("ldmatrix.sync.aligned.m8n8.x4.shared.b16 {%0,%1,%2,%3}, [%4];"
                 : "=r"(r[0]), "=r"(r[1]), "=r"(r[2]), "=r"(r[3]) : "r"(addr));
}
__device__ __forceinline__ void mma16816(float* c, const uint32_t* a, const uint32_t* b) {
    asm volatile("mma.sync.aligned.m16n8k16.row.col.f32.bf16.bf16.f32 "
                 "{%0,%1,%2,%3}, {%4,%5,%6,%7}, {%8,%9}, {%0,%1,%2,%3};"
                 : "+f"(c[0]), "+f"(c[1]), "+f"(c[2]), "+f"(c[3])
                 : "r"(a[0]), "r"(a[1]), "r"(a[2]), "r"(a[3]), "r"(b[0]), "r"(b[1]));
}
__device__ __forceinline__ void cp16(uint32_t dst, const void* src) {
    asm volatile("cp.async.cg.shared.global [%0], [%1], 16;" :: "r"(dst), "l"(src));
}
#define CP_COMMIT() asm volatile("cp.async.commit_group;" ::: "memory")
#define CP_WAIT(N)  asm volatile("cp.async.wait_group %0;" :: "n"(N) : "memory")

__device__ __forceinline__ uint32_t pack_hi(float a, float b) {
    __nv_bfloat16 ha = __float2bfloat16(a), hb = __float2bfloat16(b);
    return (uint32_t)__bfloat16_as_ushort(ha) | ((uint32_t)__bfloat16_as_ushort(hb) << 16);
}
__device__ __forceinline__ uint32_t pack_lo(float a, float b) {
    __nv_bfloat16 ha = __float2bfloat16(a), hb = __float2bfloat16(b);
    __nv_bfloat16 la = __float2bfloat16(a - __bfloat162float(ha));
    __nv_bfloat16 lb = __float2bfloat16(b - __bfloat162float(hb));
    return (uint32_t)__bfloat16_as_ushort(la) | ((uint32_t)__bfloat16_as_ushort(lb) << 16);
}

// ---------------- CSR build ----------------
__global__ void k_zero_deg() {
    int i = blockIdx.x * blockDim.x + threadIdx.x;
    if (i < N_NODES) g_deg[i] = 0;
}
__global__ void k_hist(const int* __restrict__ dst) {
    int e = blockIdx.x * blockDim.x + threadIdx.x;
    if (e < N_EDGES) atomicAdd(&g_deg[dst[e]], 1);
}
// phase 1: per-block exclusive scan of 1024 deg entries, block sum -> g_bsum
__global__ void k_scan1() {
    __shared__ int sh[1024];
    int b = blockIdx.x, t = threadIdx.x;
    int i = b * 1024 + t;
    int v = (i < N_NODES) ? g_deg[i] : 0;
    sh[t] = v;
    __syncthreads();
    #pragma unroll
    for (int off = 1; off < 1024; off <<= 1) {
        int x = (t >= off) ? sh[t - off] : 0;
        __syncthreads();
        sh[t] += x;
        __syncthreads();
    }
    if (i < N_NODES) g_rowptr[i] = sh[t] - v;   // block-local exclusive
    if (t == 1023) g_bsum[b] = sh[1023];
}
// phase 2: exclusive scan of block sums (<=128)
__global__ void k_scan2(int nblocks) {
    __shared__ int sh[128];
    int t = threadIdx.x;
    int v = (t < nblocks) ? g_bsum[t] : 0;
    sh[t] = v;
    __syncthreads();
    #pragma unroll
    for (int off = 1; off < 128; off <<= 1) {
        int x = (t >= off) ? sh[t - off] : 0;
        __syncthreads();
        sh[t] += x;
        __syncthreads();
    }
    g_boff[t] = sh[t] - v;
    if (t == nblocks - 1) g_boff[128] = sh[t];
}
// phase 3: add offsets, fill cursor/invdeg/rowptr[N]
__global__ void k_scan3() {
    int b = blockIdx.x, t = threadIdx.x;
    int i = b * 1024 + t;
    if (i < N_NODES) {
        int rp = g_rowptr[i] + g_boff[b];
        g_rowptr[i] = rp;
        g_cursor[i] = rp;
        g_invdeg[i] = 1.0f / fmaxf((float)g_deg[i], 1.0f);
    }
    if (b == 0 && t == 0) g_rowptr[N_NODES] = g_boff[128];
}
__global__ void k_scatter(const int* __restrict__ dst, const int* __restrict__ src) {
    int e = blockIdx.x * blockDim.x + threadIdx.x;
    if (e < N_EDGES) {
        int pos = atomicAdd(&g_cursor[dst[e]], 1);
        g_eid[pos] = e;
        g_csr_src[pos] = src[e];
    }
}

// ---------------- per-edge coefficients in CSR order ----------------
__global__ void k_coeff(const int* __restrict__ etype, const float* __restrict__ enorm,
                        const float4* __restrict__ att) {
    int p = blockIdx.x * blockDim.x + threadIdx.x;
    if (p >= N_EDGES) return;
    int e = g_eid[p];
    float4 a = att[etype[e]];
    float n = enorm[e];
    g_csr_coeff[p] = make_float4(a.x * n, a.y * n, a.z * n, a.w * n);
}

// ---------------- embedding gather: h0 fp32 + A1 root cols bf16 ----------------
__global__ void k_gather(const int* __restrict__ entity, const float4* __restrict__ tbl) {
    int t = blockIdx.x * blockDim.x + threadIdx.x;
    if (t >= N_NODES * 32) return;
    int node = t >> 5;
    int lane = t & 31;
    int ent = entity[node];
    float4 v = tbl[(size_t)ent * 32 + lane];
    ((float4*)g_h0)[(size_t)node * 32 + lane] = v;
    size_t a = (size_t)node * KTOT + 512 + 4 * lane;
    *(uint2*)(g_A1hi + a) = make_uint2(pack_hi(v.x, v.y), pack_hi(v.z, v.w));
    *(uint2*)(g_A1lo + a) = make_uint2(pack_lo(v.x, v.y), pack_lo(v.z, v.w));
}

// ---------------- aggregation: warp per dst node -> bf16 hi/lo S columns ----------------
__global__ void k_agg(int layer) {
    int gw = (blockIdx.x * blockDim.x + threadIdx.x) >> 5;
    int lane = threadIdx.x & 31;
    if (gw >= N_NODES) return;
    const float4* x4 = (const float4*)(layer == 0 ? g_h0 : g_h1);
    __nv_bfloat16* Ahi = (layer == 0) ? g_A1hi : g_A2hi;
    __nv_bfloat16* Alo = (layer == 0) ? g_A1lo : g_A2lo;
    int beg = g_rowptr[gw], end = g_rowptr[gw + 1];
    float4 s0 = make_float4(0.f, 0.f, 0.f, 0.f);
    float4 s1 = s0, s2 = s0, s3 = s0;
    int p = beg;
    for (; p + 2 <= end; p += 2) {
        float4 ca = g_csr_coeff[p];
        float4 cb = g_csr_coeff[p + 1];
        int sa = g_csr_src[p];
        int sb = g_csr_src[p + 1];
        float4 xa = x4[(size_t)sa * 32 + lane];
        float4 xb = x4[(size_t)sb * 32 + lane];
        s0.x = fmaf(ca.x, xa.x, s0.x); s0.y = fmaf(ca.x, xa.y, s0.y);
        s0.z = fmaf(ca.x, xa.z, s0.z); s0.w = fmaf(ca.x, xa.w, s0.w);
        s1.x = fmaf(ca.y, xa.x, s1.x); s1.y = fmaf(ca.y, xa.y, s1.y);
        s1.z = fmaf(ca.y, xa.z, s1.z); s1.w = fmaf(ca.y, xa.w, s1.w);
        s2.x = fmaf(ca.z, xa.x, s2.x); s2.y = fmaf(ca.z, xa.y, s2.y);
        s2.z = fmaf(ca.z, xa.z, s2.z); s2.w = fmaf(ca.z, xa.w, s2.w);
        s3.x = fmaf(ca.w, xa.x, s3.x); s3.y = fmaf(ca.w, xa.y, s3.y);
        s3.z = fmaf(ca.w, xa.z, s3.z); s3.w = fmaf(ca.w, xa.w, s3.w);
        s0.x = fmaf(cb.x, xb.x, s0.x); s0.y = fmaf(cb.x, xb.y, s0.y);
        s0.z = fmaf(cb.x, xb.z, s0.z); s0.w = fmaf(cb.x, xb.w, s0.w);
        s1.x = fmaf(cb.y, xb.x, s1.x); s1.y = fmaf(cb.y, xb.y, s1.y);
        s1.z = fmaf(cb.y, xb.z, s1.z); s1.w = fmaf(cb.y, xb.w, s1.w);
        s2.x = fmaf(cb.z, xb.x, s2.x); s2.y = fmaf(cb.z, xb.y, s2.y);
        s2.z = fmaf(cb.z, xb.z, s2.z); s2.w = fmaf(cb.z, xb.w, s2.w);
        s3.x = fmaf(cb.w, xb.x, s3.x); s3.y = fmaf(cb.w, xb.y, s3.y);
        s3.z = fmaf(cb.w, xb.z, s3.z); s3.w = fmaf(cb.w, xb.w, s3.w);
    }
    if (p < end) {
        float4 c = g_csr_coeff[p];
        int sn = g_csr_src[p];
        float4 xv = x4[(size_t)sn * 32 + lane];
        s0.x = fmaf(c.x, xv.x, s0.x); s0.y = fmaf(c.x, xv.y, s0.y);
        s0.z = fmaf(c.x, xv.z, s0.z); s0.w = fmaf(c.x, xv.w, s0.w);
        s1.x = fmaf(c.y, xv.x, s1.x); s1.y = fmaf(c.y, xv.y, s1.y);
        s1.z = fmaf(c.y, xv.z, s1.z); s1.w = fmaf(c.y, xv.w, s1.w);
        s2.x = fmaf(c.z, xv.x, s2.x); s2.y = fmaf(c.z, xv.y, s2.y);
        s2.z = fmaf(c.z, xv.z, s2.z); s2.w = fmaf(c.z, xv.w, s2.w);
        s3.x = fmaf(c.w, xv.x, s3.x); s3.y = fmaf(c.w, xv.y, s3.y);
        s3.z = fmaf(c.w, xv.z, s3.z); s3.w = fmaf(c.w, xv.w, s3.w);
    }
    float d = g_invdeg[gw];
    s0.x *= d; s0.y *= d; s0.z *= d; s0.w *= d;
    s1.x *= d; s1.y *= d; s1.z *= d; s1.w *= d;
    s2.x *= d; s2.y *= d; s2.z *= d; s2.w *= d;
    s3.x *= d; s3.y *= d; s3.z *= d; s3.w *= d;
    size_t base = (size_t)gw * KTOT + 4 * lane;
    *(uint2*)(Ahi + base)       = make_uint2(pack_hi(s0.x, s0.y), pack_hi(s0.z, s0.w));
    *(uint2*)(Alo + base)       = make_uint2(pack_lo(s0.x, s0.y), pack_lo(s0.z, s0.w));
    *(uint2*)(Ahi + base + 128) = make_uint2(pack_hi(s1.x, s1.y), pack_hi(s1.z, s1.w));
    *(uint2*)(Alo + base + 128) = make_uint2(pack_lo(s1.x, s1.y), pack_lo(s1.z, s1.w));
    *(uint2*)(Ahi + base + 256) = make_uint2(pack_hi(s2.x, s2.y), pack_hi(s2.z, s2.w));
    *(uint2*)(Alo + base + 256) = make_uint2(pack_lo(s2.x, s2.y), pack_lo(s2.z, s2.w));
    *(uint2*)(Ahi + base + 384) = make_uint2(pack_hi(s3.x, s3.y), pack_hi(s3.z, s3.w));
    *(uint2*)(Alo + base + 384) = make_uint2(pack_lo(s3.x, s3.y), pack_lo(s3.z, s3.w));
}

// ---------------- weight split: W[k][n] -> Whi/Wlo [n][k] bf16 ----------------
__global__ void k_prepw(const float* __restrict__ basis, const float* __restrict__ root) {
    int idx = blockIdx.x * blockDim.x + threadIdx.x;
    if (idx >= 128 * KTOT) return;
    int n = idx / KTOT;
    int k = idx % KTOT;
    float w = (k < 512) ? basis[(size_t)k * 128 + n] : root[(size_t)(k - 512) * 128 + n];
    __nv_bfloat16 hi = __float2bfloat16(w);
    __nv_bfloat16 lo = __float2bfloat16(w - __bfloat162float(hi));
    g_Whi[n * KTOT + k] = hi;
    g_Wlo[n * KTOT + k] = lo;
}

// ---------------- HMMA GEMM, cp.async double-buffered ----------------
// 128x128 tile, BK=32, 8 warps (2M x 4N), warp tile 64x32.
// smem: per buffer 4 tiles of 128 rows x 40 bf16 (80B row, conflict-free ldmatrix).
#define TILE_B 10240                    // one tile bytes
#define BUF_B  (4 * TILE_B)             // A_hi, A_lo, B_hi, B_lo
#define SMEM_GEMM (2 * BUF_B)           // 81920

__global__ __launch_bounds__(256) void k_gemm_mma(
    int layer, const float* __restrict__ bias, float* __restrict__ out_param, int do_relu)
{
    extern __shared__ char smem[];
    uint32_t sbase = smem_u32(smem);
    const __nv_bfloat16* Ahi = (layer == 0) ? g_A1hi : g_A2hi;
    const __nv_bfloat16* Alo = (layer == 0) ? g_A1lo : g_A2lo;
    float* out = (layer == 0) ? g_h1 : out_param;

    int tid = threadIdx.x;
    int wid = tid >> 5;
    int lane = tid & 31;
    int bm = blockIdx.x * 128;
    int wm0 = (wid >> 2) * 64;
    int wn0 = (wid & 3) * 32;

    float acc[4][4][4];
    #pragma unroll
    for (int i = 0; i < 4; i++)
        #pragma unroll
        for (int j = 0; j < 4; j++)
            #pragma unroll
            for (int q = 0; q < 4; q++) acc[i][j][q] = 0.f;

    // per-thread load indices: 512 16B-chunks per tile section, 2 per thread
    int lr = tid >> 1;                 // row 0..127
    int lc0 = (tid & 1) * 2;           // chunk 0/2 -> +1 for second
    int gmr = bm + lr; if (gmr >= N_NODES) gmr = 0;   // dummy row for tail
    // ldmatrix lane addressing (same as R3)
    uint32_t a_off = (uint32_t)(lane & 15) * 80 + (uint32_t)(lane >> 4) * 16;
    int bg = lane >> 3;
    uint32_t b_off = (uint32_t)((bg >> 1) * 8 + (lane & 7)) * 80 + (uint32_t)(bg & 1) * 16;

    // chunk loader: sections 0..3 = A_hi, A_lo, B_hi, B_lo
    auto load_chunk = [&](int ch, int buf) {
        int kc = ch * 32;
        uint32_t bo = sbase + buf * BUF_B;
        uint32_t drow = (uint32_t)lr * 80;
        #pragma unroll
        for (int c = 0; c < 2; c++) {
            int cc = lc0 + c;                      // 16B chunk 0..3 within row
            uint32_t dof = drow + cc * 16;
            int eof = kc + cc * 8;                 // element offset within K row
            cp16(bo + dof,              Ahi + (size_t)gmr * KTOT + eof);
            cp16(bo + TILE_B + dof,     Alo + (size_t)gmr * KTOT + eof);
            cp16(bo + 2 * TILE_B + dof, g_Whi + lr * KTOT + eof);
            cp16(bo + 3 * TILE_B + dof, g_Wlo + lr * KTOT + eof);
        }
    };

    load_chunk(0, 0);
    CP_COMMIT();

    #pragma unroll 1
    for (int ch = 0; ch < 20; ch++) {
        int buf = ch & 1;
        if (ch < 19) {
            load_chunk(ch + 1, buf ^ 1);
            CP_COMMIT();
            CP_WAIT(1);
        } else {
            CP_WAIT(0);
        }
        __syncthreads();

        uint32_t a_hi_base = sbase + buf * BUF_B;
        uint32_t a_lo_base = a_hi_base + TILE_B;
        uint32_t b_hi_base = a_hi_base + 2 * TILE_B;
        uint32_t b_lo_base = a_hi_base + 3 * TILE_B;

        #pragma unroll
        for (int kk = 0; kk < 2; kk++) {
            uint32_t kb = (uint32_t)kk * 32;
            uint32_t ahi[4][4], alo[4][4];
            #pragma unroll
            for (int mf = 0; mf < 4; mf++) {
                uint32_t o = (uint32_t)(wm0 + mf * 16) * 80 + a_off + kb;
                ldm_x4(ahi[mf], a_hi_base + o);
                ldm_x4(alo[mf], a_lo_base + o);
            }
            uint32_t bhi[4][2], blo[4][2];
            #pragma unroll
            for (int pr = 0; pr < 2; pr++) {
                uint32_t o = (uint32_t)(wn0 + pr * 16) * 80 + b_off + kb;
                uint32_t th[4], tl[4];
                ldm_x4(th, b_hi_base + o);
                ldm_x4(tl, b_lo_base + o);
                bhi[pr * 2][0] = th[0]; bhi[pr * 2][1] = th[1];
                bhi[pr * 2 + 1][0] = th[2]; bhi[pr * 2 + 1][1] = th[3];
                blo[pr * 2][0] = tl[0]; blo[pr * 2][1] = tl[1];
                blo[pr * 2 + 1][0] = tl[2]; blo[pr * 2 + 1][1] = tl[3];
            }
            #pragma unroll
            for (int mf = 0; mf < 4; mf++)
                #pragma unroll
                for (int nf = 0; nf < 4; nf++) {
                    mma16816(acc[mf][nf], ahi[mf], bhi[nf]);
                    mma16816(acc[mf][nf], ahi[mf], blo[nf]);
                    mma16816(acc[mf][nf], alo[mf], bhi[nf]);
                }
        }
        __syncthreads();
    }

    // epilogue: bias + optional relu; layer 0 also writes A2 root columns (bf16 hi/lo)
    int qm = lane >> 2;
    int qn = (lane & 3) * 2;
    #pragma unroll
    for (int nf = 0; nf < 4; nf++) {
        int n = wn0 + nf * 8 + qn;
        float b0 = bias[n], b1 = bias[n + 1];
        #pragma unroll
        for (int mf = 0; mf < 4; mf++) {
            int m0 = bm + wm0 + mf * 16 + qm;
            float2 lo = make_float2(acc[mf][nf][0] + b0, acc[mf][nf][1] + b1);
            float2 hi = make_float2(acc[mf][nf][2] + b0, acc[mf][nf][3] + b1);
            if (do_relu) {
                lo.x = fmaxf(lo.x, 0.f); lo.y = fmaxf(lo.y, 0.f);
                hi.x = fmaxf(hi.x, 0.f); hi.y = fmaxf(hi.y, 0.f);
            }
            if (m0 < N_NODES) {
                *(float2*)(out + (size_t)m0 * 128 + n) = lo;
                if (layer == 0) {
                    size_t a = (size_t)m0 * KTOT + 512 + n;
                    *(uint32_t*)(g_A2hi + a) = pack_hi(lo.x, lo.y);
                    *(uint32_t*)(g_A2lo + a) = pack_lo(lo.x, lo.y);
                }
            }
            if (m0 + 8 < N_NODES) {
                *(float2*)(out + (size_t)(m0 + 8) * 128 + n) = hi;
                if (layer == 0) {
                    size_t a = (size_t)(m0 + 8) * KTOT + 512 + n;
                    *(uint32_t*)(g_A2hi + a) = pack_hi(hi.x, hi.y);
                    *(uint32_t*)(g_A2lo + a) = pack_lo(hi.x, hi.y);
                }
            }
        }
    }
}

// ---------------- relation_emb passthrough ----------------
__global__ void k_copyrel(const float* __restrict__ rel, float* __restrict__ out) {
    int i = blockIdx.x * blockDim.x + threadIdx.x;
    if (i < 500 * 128) out[i] = rel[i];
}

// ---------------- launch ----------------
extern "C" void kernel_launch(void* const* d_in, const int* in_sizes, int n_in,
                              void* d_out, int out_size) {
    const int*   entity       = (const int*)d_in[0];
    const int*   edge_index   = (const int*)d_in[1];
    const int*   edge_type    = (const int*)d_in[2];
    const float* edge_norm    = (const float*)d_in[3];
    // d_in[4] = DAD_rel (unused by reference output)
    const float* entity_table = (const float*)d_in[5];
    const float* relation_emb = (const float*)d_in[6];
    const float* basis1 = (const float*)d_in[7];
    const float* att1   = (const float*)d_in[8];
    const float* root1  = (const float*)d_in[9];
    const float* bias1  = (const float*)d_in[10];
    const float* basis2 = (const float*)d_in[11];
    const float* att2   = (const float*)d_in[12];
    const float* root2  = (const float*)d_in[13];
    const float* bias2  = (const float*)d_in[14];

    const int* src = edge_index;
    const int* dst = edge_index + N_EDGES;
    float* out = (float*)d_out;

    static int smem_set = 0;
    if (!smem_set) {
        cudaFuncSetAttribute(k_gemm_mma, cudaFuncAttributeMaxDynamicSharedMemorySize, SMEM_GEMM);
        smem_set = 1;
    }

    int scan_blocks = (N_NODES + 1023) / 1024;   // 98

    // CSR by dst
    k_zero_deg<<<(N_NODES + 255) / 256, 256>>>();
    k_hist<<<(N_EDGES + 255) / 256, 256>>>(dst);
    k_scan1<<<scan_blocks, 1024>>>();
    k_scan2<<<1, 128>>>(scan_blocks);
    k_scan3<<<scan_blocks, 1024>>>();
    k_scatter<<<(N_EDGES + 255) / 256, 256>>>(dst, src);

    // h0 = entity_table[entity] (+ A1 root cols)
    k_gather<<<(N_NODES * 32 + 255) / 256, 256>>>(entity, (const float4*)entity_table);

    int gemm_blocks = (N_NODES + 127) / 128;   // 782

    // layer 1 (relu)
    k_coeff<<<(N_EDGES + 255) / 256, 256>>>(edge_type, edge_norm, (const float4*)att1);
    k_agg<<<(N_NODES * 32 + 255) / 256, 256>>>(0);
    k_prepw<<<(128 * KTOT + 255) / 256, 256>>>(basis1, root1);
    k_gemm_mma<<<gemm_blocks, 256, SMEM_GEMM>>>(0, bias1, nullptr, 1);

    // layer 2 (no relu) -> d_out
    k_coeff<<<(N_EDGES + 255) / 256, 256>>>(edge_type, edge_norm, (const float4*)att2);
    k_agg<<<(N_NODES * 32 + 255) / 256, 256>>>(1);
    k_prepw<<<(128 * KTOT + 255) / 256, 256>>>(basis2, root2);
    k_gemm_mma<<<gemm_blocks, 256, SMEM_GEMM>>>(1, bias2, out, 0);

    // append relation_emb
    k_copyrel<<<(500 * 128 + 255) / 256, 256>>>(relation_emb, out + (size_t)N_NODES * DIM);
}